// round 12
// baseline (speedup 1.0000x reference)
#include <cuda_runtime.h>
#include <cuda_fp16.h>
#include <cstdint>

// -------- problem sizes --------
#define M_TOTAL 8192
#define N_TOTAL 11008
#define K_TOTAL 4096
#define BM 128
#define BN 256
#define BK 64
#define STAGES 4
#define NUM_KIT (K_TOTAL / BK)   // 64
#define MT (M_TOTAL / BM)        // 64
#define NT (N_TOTAL / BN)        // 43
#define NUM_TILES (MT * NT)      // 2752
#define NUM_CTAS 148             // 1 CTA per SM
#define GROUPM 16
#define ATILE_BYTES (BM * BK * 2)            // 16384
#define BTILE_BYTES (BN * BK * 2)            // 32768
#define STAGE_BYTES (ATILE_BYTES + BTILE_BYTES)  // 49152
#define NEXT_OFF (STAGES * STAGE_BYTES)      // smem offset of next-tile broadcast
#define SMEM_BYTES (STAGES * STAGE_BYTES + 16)   // 196624

// pack grid split
#define XCHUNKS (M_TOTAL * K_TOTAL / 8)      // 4194304
#define WCHUNKS (N_TOTAL * K_TOTAL / 8)      // 5636096
#define XBLOCKS (XCHUNKS / 256)              // 16384
#define WBLOCKS (WCHUNKS / 256)              // 22016

// dequantized fp16 operands (device scratch; no allocation)
__device__ __align__(128) __half g_Xh[(size_t)M_TOTAL * K_TOTAL];   // 64 MB
__device__ __align__(128) __half g_Wh[(size_t)N_TOTAL * K_TOTAL];   // 86 MB
__device__ unsigned g_tile_counter;

// -------- helpers --------
__device__ __forceinline__ uint32_t smem_u32(const void* p) {
    uint32_t a;
    asm("{ .reg .u64 t; cvta.to.shared.u64 t, %1; cvt.u32.u64 %0, t; }" : "=r"(a) : "l"(p));
    return a;
}

__device__ __forceinline__ void cp16(uint32_t s, const void* g) {
    asm volatile("cp.async.cg.shared.global [%0], [%1], 16;" :: "r"(s), "l"(g) : "memory");
}
#define CP_COMMIT() asm volatile("cp.async.commit_group;" ::: "memory")
#define CP_WAIT(n)  asm volatile("cp.async.wait_group %0;" :: "n"(n) : "memory")

__device__ __forceinline__ void ldm_x4(uint32_t* r, uint32_t a) {
    asm volatile("ldmatrix.sync.aligned.m8n8.x4.shared.b16 {%0,%1,%2,%3}, [%4];"
        : "=r"(r[0]), "=r"(r[1]), "=r"(r[2]), "=r"(r[3]) : "r"(a));
}

__device__ __forceinline__ void mma16816(float* c, const uint32_t* a, uint32_t b0, uint32_t b1) {
    asm volatile("mma.sync.aligned.m16n8k16.row.col.f32.f16.f16.f32 "
        "{%0,%1,%2,%3}, {%4,%5,%6,%7}, {%8,%9}, {%0,%1,%2,%3};"
        : "+f"(c[0]), "+f"(c[1]), "+f"(c[2]), "+f"(c[3])
        : "r"(a[0]), "r"(a[1]), "r"(a[2]), "r"(a[3]), "r"(b0), "r"(b1));
}

// tile id -> (mt, nt) with m-banding for L2 locality
__device__ __forceinline__ void decode_tile(int id, int& mt, int& nt) {
    const int panel = id / (GROUPM * NT);
    const int rem   = id % (GROUPM * NT);
    mt = panel * GROUPM + (rem % GROUPM);
    nt = rem / GROUPM;
}

// -------- fused prep: pack x, dequant+pack w, init tile counter --------
__global__ void prep_kernel(const float* __restrict__ x,
                            const int* __restrict__ wq,
                            const float* __restrict__ ws,
                            const float* __restrict__ wz) {
    if (blockIdx.x == 0 && threadIdx.x == 0) g_tile_counter = NUM_CTAS;

    if (blockIdx.x < XBLOCKS) {
        size_t idx = (size_t)blockIdx.x * blockDim.x + threadIdx.x;
        const float4* s = reinterpret_cast<const float4*>(x) + idx * 2;
        float4 a = s[0], b = s[1];
        __half2 h0 = __floats2half2_rn(a.x, a.y);
        __half2 h1 = __floats2half2_rn(a.z, a.w);
        __half2 h2 = __floats2half2_rn(b.x, b.y);
        __half2 h3 = __floats2half2_rn(b.z, b.w);
        uint4 u;
        u.x = *(uint32_t*)&h0; u.y = *(uint32_t*)&h1;
        u.z = *(uint32_t*)&h2; u.w = *(uint32_t*)&h3;
        reinterpret_cast<uint4*>(g_Xh)[idx] = u;
    } else {
        size_t idx = (size_t)(blockIdx.x - XBLOCKS) * blockDim.x + threadIdx.x;
        const int o  = (int)(idx >> 9);          // 512 chunks per output row
        const int kc = (int)(idx & 511);
        const int g  = (kc * 8) >> 7;            // group of 128 k's
        const float s = ws[(size_t)o * 32 + g];
        const float z = wz[(size_t)o * 32 + g];

        int4 q = *reinterpret_cast<const int4*>(wq + (size_t)o * 2048 + kc * 4);
        const int* qi = reinterpret_cast<const int*>(&q);

        uint32_t parts[4];
#pragma unroll
        for (int j = 0; j < 4; j++) {
            int b = qi[j];
            float hi = (float)((b >> 4) & 0xF);   // k = 2j (high nibble first)
            float lo = (float)(b & 0xF);          // k = 2j+1
            __half2 h = __floats2half2_rn(fmaf(hi, s, z), fmaf(lo, s, z));
            parts[j] = *(uint32_t*)&h;
        }
        uint4 u; u.x = parts[0]; u.y = parts[1]; u.z = parts[2]; u.w = parts[3];
        reinterpret_cast<uint4*>(g_Wh)[idx] = u;
    }
}

// -------- persistent GEMM: 128x256 tile per SM, 8 warps of 64x64,
// -------- rotated 4-stage pipeline --------
__global__ void __launch_bounds__(256, 1)
gemm_kernel(float* __restrict__ out) {
    extern __shared__ __align__(128) unsigned char smem[];
    const uint32_t sb = smem_u32(smem);
    volatile int* next_smem = reinterpret_cast<volatile int*>(smem + NEXT_OFF);
    const int tid = threadIdx.x;
    const int wid = tid >> 5, lane = tid & 31;
    const int wm = wid & 1;          // m half (0..1)
    const int wn = wid >> 1;         // n quarter (0..3)

    // per-lane ldmatrix constants (XOR swizzle by row&7)
    const int rA = wm * 64 + (lane & 15);
    const uint32_t xorA = (uint32_t)(rA & 7) << 4;
    const uint32_t hiA  = ((lane >> 4) & 1) * 16;
    const int rBbase = wn * 64 + ((lane >> 4) & 1) * 8 + (lane & 7);
    const uint32_t xorB = (uint32_t)(lane & 7) << 4;
    const uint32_t hiB  = ((lane >> 3) & 1) * 16;

    // cp.async indices: 256 threads, 32 rows per wave
    const int ld_row0 = tid >> 3;        // 0..31
    const int ld_c    = tid & 7;

    // ---- load-side state (runs ahead across tile boundaries) ----
    int ld_tile = blockIdx.x;
    int ld_kit  = 0;
    const __half* Ag_ld;
    const __half* Bg_ld;
    {
        int mt, nt; decode_tile(ld_tile, mt, nt);
        Ag_ld = g_Xh + (size_t)mt * BM * K_TOTAL;
        Bg_ld = g_Wh + (size_t)nt * BN * K_TOTAL;
    }

    auto issue_load = [&](int slot) {
        if (ld_tile < NUM_TILES) {
            const uint32_t sA = sb + slot * STAGE_BYTES;
            const uint32_t sB = sA + ATILE_BYTES;
            const __half* gA = Ag_ld + (size_t)ld_kit * BK;
            const __half* gB = Bg_ld + (size_t)ld_kit * BK;
#pragma unroll
            for (int w = 0; w < 4; w++) {        // A: 128 rows
                const int row = ld_row0 + w * 32;
                const uint32_t soff = (uint32_t)row * 128 +
                    (((uint32_t)ld_c * 16) ^ (((uint32_t)row & 7) << 4));
                cp16(sA + soff, gA + (size_t)row * K_TOTAL + ld_c * 8);
            }
#pragma unroll
            for (int w = 0; w < 8; w++) {        // B: 256 rows
                const int row = ld_row0 + w * 32;
                const uint32_t soff = (uint32_t)row * 128 +
                    (((uint32_t)ld_c * 16) ^ (((uint32_t)row & 7) << 4));
                cp16(sB + soff, gB + (size_t)row * K_TOTAL + ld_c * 8);
            }
        }
        if (++ld_kit == NUM_KIT) {
            ld_kit = 0;
            ld_tile = *next_smem;               // popped at current tile's kit 0
            if (ld_tile < NUM_TILES) {
                int mt, nt; decode_tile(ld_tile, mt, nt);
                Ag_ld = g_Xh + (size_t)mt * BM * K_TOTAL;
                Bg_ld = g_Wh + (size_t)nt * BN * K_TOTAL;
            }
        }
    };

    float acc[4][8][4];
#pragma unroll
    for (int i = 0; i < 4; i++)
#pragma unroll
        for (int j = 0; j < 8; j++)
#pragma unroll
            for (int r = 0; r < 4; r++) acc[i][j][r] = 0.f;

    uint32_t afr[2][4][4];
    uint32_t bfr[2][4][4];
    auto load_frags = [&](int buf, int kk, uint32_t sA, uint32_t sB) {
#pragma unroll
        for (int mi = 0; mi < 4; mi++) {
            uint32_t addr = sA + (uint32_t)(rA + mi * 16) * 128 +
                            (((uint32_t)(kk * 32) + hiA) ^ xorA);
            ldm_x4(afr[buf][mi], addr);
        }
#pragma unroll
        for (int nj = 0; nj < 4; nj++) {
            uint32_t addr = sB + (uint32_t)(rBbase + nj * 16) * 128 +
                            (((uint32_t)(kk * 32) + hiB) ^ xorB);
            ldm_x4(bfr[buf][nj], addr);
        }
    };

    auto mma_step = [&](int buf) {
#pragma unroll
        for (int mi = 0; mi < 4; mi++) {
#pragma unroll
            for (int ni = 0; ni < 8; ni++) {
                const uint32_t* bp = bfr[buf][ni >> 1];
                const int sub = (ni & 1) * 2;
                mma16816(acc[mi][ni], afr[buf][mi], bp[sub], bp[sub + 1]);
            }
        }
    };

    // prologue: stages 0..2 in flight; stage 0 resident; prime kk0 frags
    issue_load(0); CP_COMMIT();
    issue_load(1); CP_COMMIT();
    issue_load(2); CP_COMMIT();
    CP_WAIT(2);
    __syncthreads();
    int slot_ld = 3;     // next slot to fill
    int slot_cur = 0;    // slot being computed
    uint32_t curA = sb, curB = sb + ATILE_BYTES;
    load_frags(0, 0, curA, curB);          // kk0 of very first kit

    int cur = blockIdx.x;
    while (cur < NUM_TILES) {
        int mt, nt; decode_tile(cur, mt, nt);

        for (int kit = 0; kit < NUM_KIT; kit++) {
            // kk0 frags already in buf0 (prefetched at previous boundary)
#pragma unroll
            for (int kk = 0; kk < 3; kk++) {
                load_frags((kk + 1) & 1, kk + 1, curA, curB);
                mma_step(kk & 1);
            }

            // rotated boundary (hidden under kk2/kk3 HMMA drain):
            // issue stage s+3 first so its LDGSTS overlap the wait+barrier.
            // Target slot was last read in kit-1; a collective barrier has
            // intervened, so the early write is race-free.
            issue_load(slot_ld);
            CP_COMMIT();
            slot_ld = (slot_ld == STAGES - 1) ? 0 : slot_ld + 1;
            CP_WAIT(2);          // retire stage s+1's group
            __syncthreads();     // => ALL threads' copies of stage s+1 done
            if (kit == 0 && tid == 0)
                *next_smem = (int)atomicAdd(&g_tile_counter, 1u);

            // advance to next stage and prefetch its kk0 BEFORE kk3's MMAs
            slot_cur = (slot_cur == STAGES - 1) ? 0 : slot_cur + 1;
            curA = sb + slot_cur * STAGE_BYTES;
            curB = curA + ATILE_BYTES;
            load_frags(0, 0, curA, curB);   // buf0 free since kk2's mma_step

            mma_step(1);         // kk3
        }

        // epilogue (next tile's loads + kk0 frags already in flight/registers)
        const int orow0 = mt * BM + wm * 64 + (lane >> 2);
        const int ocol0 = nt * BN + wn * 64 + (lane & 3) * 2;
#pragma unroll
        for (int mi = 0; mi < 4; mi++) {
#pragma unroll
            for (int ni = 0; ni < 8; ni++) {
                const int r0 = orow0 + mi * 16;
                const int c0 = ocol0 + ni * 8;
                float2 v0 = make_float2(acc[mi][ni][0], acc[mi][ni][1]);
                float2 v1 = make_float2(acc[mi][ni][2], acc[mi][ni][3]);
                *reinterpret_cast<float2*>(out + (size_t)r0 * N_TOTAL + c0)       = v0;
                *reinterpret_cast<float2*>(out + (size_t)(r0 + 8) * N_TOTAL + c0) = v1;
#pragma unroll
                for (int r = 0; r < 4; r++) acc[mi][ni][r] = 0.f;
            }
        }

        cur = *next_smem;   // stable since this tile's kit 0
    }
}

// -------- launch --------
extern "C" void kernel_launch(void* const* d_in, const int* in_sizes, int n_in,
                              void* d_out, int out_size) {
    const float* x  = (const float*)d_in[0];
    const int*   wq = (const int*)d_in[1];
    const float* ws = (const float*)d_in[2];
    const float* wz = (const float*)d_in[3];
    float* out = (float*)d_out;

    cudaFuncSetAttribute(gemm_kernel, cudaFuncAttributeMaxDynamicSharedMemorySize, SMEM_BYTES);

    prep_kernel<<<XBLOCKS + WBLOCKS, 256>>>(x, wq, ws, wz);
    gemm_kernel<<<NUM_CTAS, 256, SMEM_BYTES>>>(out);
}

// round 13
// speedup vs baseline: 1.0625x; 1.0625x over previous
#include <cuda_runtime.h>
#include <cuda_fp16.h>
#include <cstdint>

// -------- problem sizes --------
#define M_TOTAL 8192
#define N_TOTAL 11008
#define K_TOTAL 4096
#define BM 128
#define BN 128
#define BK 64
#define STAGES 3
#define NUM_KIT (K_TOTAL / BK)   // 64
#define MT (M_TOTAL / BM)        // 64
#define NT (N_TOTAL / BN)        // 86
#define NUM_TILES (MT * NT)      // 5504
#define NUM_CTAS 296             // 148 SMs x 2 CTAs
#define GROUPM 16
#define ATILE_BYTES (BM * BK * 2)            // 16384
#define STAGE_BYTES (2 * ATILE_BYTES)        // 32768 (A + B)
#define NEXT_OFF (STAGES * STAGE_BYTES)      // smem offset of next-tile broadcast
#define SMEM_BYTES (STAGES * STAGE_BYTES + 16)

// pack grid split
#define XCHUNKS (M_TOTAL * K_TOTAL / 8)      // 4194304
#define WCHUNKS (N_TOTAL * K_TOTAL / 8)      // 5636096
#define XBLOCKS (XCHUNKS / 256)              // 16384
#define WBLOCKS (WCHUNKS / 256)              // 22016

// dequantized fp16 operands (device scratch; no allocation)
__device__ __align__(128) __half g_Xh[(size_t)M_TOTAL * K_TOTAL];   // 64 MB
__device__ __align__(128) __half g_Wh[(size_t)N_TOTAL * K_TOTAL];   // 86 MB
__device__ unsigned g_tile_counter;

// -------- helpers --------
__device__ __forceinline__ uint32_t smem_u32(const void* p) {
    uint32_t a;
    asm("{ .reg .u64 t; cvta.to.shared.u64 t, %1; cvt.u32.u64 %0, t; }" : "=r"(a) : "l"(p));
    return a;
}

__device__ __forceinline__ void cp16(uint32_t s, const void* g) {
    asm volatile("cp.async.cg.shared.global [%0], [%1], 16;" :: "r"(s), "l"(g) : "memory");
}
#define CP_COMMIT() asm volatile("cp.async.commit_group;" ::: "memory")
#define CP_WAIT(n)  asm volatile("cp.async.wait_group %0;" :: "n"(n) : "memory")

__device__ __forceinline__ void ldm_x4(uint32_t* r, uint32_t a) {
    asm volatile("ldmatrix.sync.aligned.m8n8.x4.shared.b16 {%0,%1,%2,%3}, [%4];"
        : "=r"(r[0]), "=r"(r[1]), "=r"(r[2]), "=r"(r[3]) : "r"(a));
}

__device__ __forceinline__ void mma16816(float* c, const uint32_t* a, uint32_t b0, uint32_t b1) {
    asm volatile("mma.sync.aligned.m16n8k16.row.col.f32.f16.f16.f32 "
        "{%0,%1,%2,%3}, {%4,%5,%6,%7}, {%8,%9}, {%0,%1,%2,%3};"
        : "+f"(c[0]), "+f"(c[1]), "+f"(c[2]), "+f"(c[3])
        : "r"(a[0]), "r"(a[1]), "r"(a[2]), "r"(a[3]), "r"(b0), "r"(b1));
}

// streaming store: output is write-once, keep it out of L2's working set
__device__ __forceinline__ void stg_cs_f2(float* p, float x, float y) {
    asm volatile("st.global.cs.v2.f32 [%0], {%1, %2};" :: "l"(p), "f"(x), "f"(y) : "memory");
}

// tile id -> (mt, nt) with m-banding for L2 locality
__device__ __forceinline__ void decode_tile(int id, int& mt, int& nt) {
    const int panel = id / (GROUPM * NT);
    const int rem   = id % (GROUPM * NT);
    mt = panel * GROUPM + (rem % GROUPM);
    nt = rem / GROUPM;
}

// -------- fused prep: pack x, dequant+pack w, init tile counter --------
__global__ void prep_kernel(const float* __restrict__ x,
                            const int* __restrict__ wq,
                            const float* __restrict__ ws,
                            const float* __restrict__ wz) {
    if (blockIdx.x == 0 && threadIdx.x == 0) g_tile_counter = NUM_CTAS;

    if (blockIdx.x < XBLOCKS) {
        // x (fp32) -> fp16 row-major, one 8-elem chunk per thread
        size_t idx = (size_t)blockIdx.x * blockDim.x + threadIdx.x;
        const float4* s = reinterpret_cast<const float4*>(x) + idx * 2;
        float4 a = s[0], b = s[1];
        __half2 h0 = __floats2half2_rn(a.x, a.y);
        __half2 h1 = __floats2half2_rn(a.z, a.w);
        __half2 h2 = __floats2half2_rn(b.x, b.y);
        __half2 h3 = __floats2half2_rn(b.z, b.w);
        uint4 u;
        u.x = *(uint32_t*)&h0; u.y = *(uint32_t*)&h1;
        u.z = *(uint32_t*)&h2; u.w = *(uint32_t*)&h3;
        reinterpret_cast<uint4*>(g_Xh)[idx] = u;
    } else {
        // int4-packed weights -> dequantized fp16 row-major, one 8-k chunk
        size_t idx = (size_t)(blockIdx.x - XBLOCKS) * blockDim.x + threadIdx.x;
        const int o  = (int)(idx >> 9);          // 512 chunks per output row
        const int kc = (int)(idx & 511);
        const int g  = (kc * 8) >> 7;            // group of 128 k's
        const float s = ws[(size_t)o * 32 + g];
        const float z = wz[(size_t)o * 32 + g];

        int4 q = *reinterpret_cast<const int4*>(wq + (size_t)o * 2048 + kc * 4);
        const int* qi = reinterpret_cast<const int*>(&q);

        uint32_t parts[4];
#pragma unroll
        for (int j = 0; j < 4; j++) {
            int b = qi[j];
            float hi = (float)((b >> 4) & 0xF);   // k = 2j (high nibble first)
            float lo = (float)(b & 0xF);          // k = 2j+1
            __half2 h = __floats2half2_rn(fmaf(hi, s, z), fmaf(lo, s, z));
            parts[j] = *(uint32_t*)&h;
        }
        uint4 u; u.x = parts[0]; u.y = parts[1]; u.z = parts[2]; u.w = parts[3];
        reinterpret_cast<uint4*>(g_Wh)[idx] = u;
    }
}

// -------- persistent GEMM: 128x128 tile, 4 warps of 64x64,
// -------- rotated pipeline:
// --------   kk0-kk2 | issue s+2; CP_WAIT(1); barrier; prefetch next kk0 | kk3
__global__ void __launch_bounds__(128, 2)
gemm_kernel(float* __restrict__ out) {
    extern __shared__ __align__(128) unsigned char smem[];
    const uint32_t sb = smem_u32(smem);
    volatile int* next_smem = reinterpret_cast<volatile int*>(smem + NEXT_OFF);
    const int tid = threadIdx.x;
    const int wid = tid >> 5, lane = tid & 31;
    const int wm = wid & 1;          // m half
    const int wn = wid >> 1;         // n half

    // per-lane ldmatrix constants (XOR swizzle by row&7)
    const int rA = wm * 64 + (lane & 15);
    const uint32_t xorA = (uint32_t)(rA & 7) << 4;
    const uint32_t hiA  = ((lane >> 4) & 1) * 16;
    const int rBbase = wn * 64 + ((lane >> 4) & 1) * 8 + (lane & 7);
    const uint32_t xorB = (uint32_t)(lane & 7) << 4;
    const uint32_t hiB  = ((lane >> 3) & 1) * 16;

    // cp.async indices: 128 threads, 16 rows per wave, 8 waves for 128 rows
    const int ld_row0 = tid >> 3;
    const int ld_c    = tid & 7;

    // ---- load-side state (runs ahead across tile boundaries) ----
    int ld_tile = blockIdx.x;
    int ld_kit  = 0;
    const __half* Ag_ld;
    const __half* Bg_ld;
    {
        int mt, nt; decode_tile(ld_tile, mt, nt);
        Ag_ld = g_Xh + (size_t)mt * BM * K_TOTAL;
        Bg_ld = g_Wh + (size_t)nt * BN * K_TOTAL;
    }

    auto issue_load = [&](int slot) {
        if (ld_tile < NUM_TILES) {
            const uint32_t sA = sb + slot * STAGE_BYTES;
            const uint32_t sB = sA + ATILE_BYTES;
            const __half* gA = Ag_ld + (size_t)ld_kit * BK;
            const __half* gB = Bg_ld + (size_t)ld_kit * BK;
#pragma unroll
            for (int w = 0; w < 8; w++) {
                const int row = ld_row0 + w * 16;
                const uint32_t soff = (uint32_t)row * 128 +
                    (((uint32_t)ld_c * 16) ^ (((uint32_t)row & 7) << 4));
                cp16(sA + soff, gA + (size_t)row * K_TOTAL + ld_c * 8);
                cp16(sB + soff, gB + (size_t)row * K_TOTAL + ld_c * 8);
            }
        }
        if (++ld_kit == NUM_KIT) {
            ld_kit = 0;
            ld_tile = *next_smem;               // popped at current tile's kit 0
            if (ld_tile < NUM_TILES) {
                int mt, nt; decode_tile(ld_tile, mt, nt);
                Ag_ld = g_Xh + (size_t)mt * BM * K_TOTAL;
                Bg_ld = g_Wh + (size_t)nt * BN * K_TOTAL;
            }
        }
    };

    float acc[4][8][4];
#pragma unroll
    for (int i = 0; i < 4; i++)
#pragma unroll
        for (int j = 0; j < 8; j++)
#pragma unroll
            for (int r = 0; r < 4; r++) acc[i][j][r] = 0.f;

    uint32_t afr[2][4][4];
    uint32_t bfr[2][4][4];
    auto load_frags = [&](int buf, int kk, uint32_t sA, uint32_t sB) {
#pragma unroll
        for (int mi = 0; mi < 4; mi++) {
            uint32_t addr = sA + (uint32_t)(rA + mi * 16) * 128 +
                            (((uint32_t)(kk * 32) + hiA) ^ xorA);
            ldm_x4(afr[buf][mi], addr);
        }
#pragma unroll
        for (int nj = 0; nj < 4; nj++) {
            uint32_t addr = sB + (uint32_t)(rBbase + nj * 16) * 128 +
                            (((uint32_t)(kk * 32) + hiB) ^ xorB);
            ldm_x4(bfr[buf][nj], addr);
        }
    };

    auto mma_step = [&](int buf) {
#pragma unroll
        for (int mi = 0; mi < 4; mi++) {
#pragma unroll
            for (int ni = 0; ni < 8; ni++) {
                const uint32_t* bp = bfr[buf][ni >> 1];
                const int sub = (ni & 1) * 2;
                mma16816(acc[mi][ni], afr[buf][mi], bp[sub], bp[sub + 1]);
            }
        }
    };

    // prologue: stages 0 and 1 in flight; stage 0 resident; prime kk0 frags
    issue_load(0); CP_COMMIT();
    issue_load(1); CP_COMMIT();
    CP_WAIT(1);
    __syncthreads();
    int slot_ld = 2;     // next slot to fill
    int slot_cur = 0;    // slot being computed
    uint32_t curA = sb, curB = sb + ATILE_BYTES;
    load_frags(0, 0, curA, curB);          // kk0 of very first kit

    int cur = blockIdx.x;
    while (cur < NUM_TILES) {
        int mt, nt; decode_tile(cur, mt, nt);

        for (int kit = 0; kit < NUM_KIT; kit++) {
            // kk0 frags already in buf0 (prefetched at previous boundary)
#pragma unroll
            for (int kk = 0; kk < 3; kk++) {
                load_frags((kk + 1) & 1, kk + 1, curA, curB);
                mma_step(kk & 1);
            }

            // rotated boundary (hidden under kk2/kk3 HMMA drain):
            // issue stage s+2 first so its LDGSTS overlap the wait+barrier.
            // Target slot was last read in kit-1; a collective barrier has
            // intervened, so the early write is race-free.
            issue_load(slot_ld);
            CP_COMMIT();
            slot_ld = (slot_ld == STAGES - 1) ? 0 : slot_ld + 1;
            CP_WAIT(1);          // retire stage s+1's group (issued a kit ago)
            __syncthreads();     // => ALL warps' copies of stage s+1 done
            if (kit == 0 && tid == 0)
                *next_smem = (int)atomicAdd(&g_tile_counter, 1u);

            // advance to next stage and prefetch its kk0 BEFORE kk3's MMAs
            slot_cur = (slot_cur == STAGES - 1) ? 0 : slot_cur + 1;
            curA = sb + slot_cur * STAGE_BYTES;
            curB = curA + ATILE_BYTES;
            load_frags(0, 0, curA, curB);   // buf0 free since kk2's mma_step

            mma_step(1);         // kk3
        }

        // epilogue: streaming fp32 stores (output is write-once; keep L2 for operands)
        const int orow0 = mt * BM + wm * 64 + (lane >> 2);
        const int ocol0 = nt * BN + wn * 64 + (lane & 3) * 2;
#pragma unroll
        for (int mi = 0; mi < 4; mi++) {
#pragma unroll
            for (int ni = 0; ni < 8; ni++) {
                const int r0 = orow0 + mi * 16;
                const int c0 = ocol0 + ni * 8;
                stg_cs_f2(out + (size_t)r0 * N_TOTAL + c0,
                          acc[mi][ni][0], acc[mi][ni][1]);
                stg_cs_f2(out + (size_t)(r0 + 8) * N_TOTAL + c0,
                          acc[mi][ni][2], acc[mi][ni][3]);
#pragma unroll
                for (int r = 0; r < 4; r++) acc[mi][ni][r] = 0.f;
            }
        }

        cur = *next_smem;   // stable since this tile's kit 0
    }
}

// -------- launch --------
extern "C" void kernel_launch(void* const* d_in, const int* in_sizes, int n_in,
                              void* d_out, int out_size) {
    const float* x  = (const float*)d_in[0];
    const int*   wq = (const int*)d_in[1];
    const float* ws = (const float*)d_in[2];
    const float* wz = (const float*)d_in[3];
    float* out = (float*)d_out;

    cudaFuncSetAttribute(gemm_kernel, cudaFuncAttributeMaxDynamicSharedMemorySize, SMEM_BYTES);

    prep_kernel<<<XBLOCKS + WBLOCKS, 256>>>(x, wq, ws, wz);
    gemm_kernel<<<NUM_CTAS, 128, SMEM_BYTES>>>(out);
}